// round 10
// baseline (speedup 1.0000x reference)
#include <cuda_runtime.h>
#include <math.h>

#define NATOMS 10000
#define NPAIR  100000

typedef unsigned long long u64;
__device__ __forceinline__ u64 pk2(float a, float b) {
    u64 r; asm("mov.b64 %0,{%1,%2};" : "=l"(r) : "f"(a), "f"(b)); return r;
}
__device__ __forceinline__ void up2(u64 v, float& a, float& b) {
    asm("mov.b64 {%0,%1},%2;" : "=f"(a), "=f"(b) : "l"(v));
}
__device__ __forceinline__ u64 fma2(u64 a, u64 b, u64 c) {
    u64 d; asm("fma.rn.f32x2 %0,%1,%2,%3;" : "=l"(d) : "l"(a), "l"(b), "l"(c)); return d;
}
__device__ __forceinline__ u64 mul2_(u64 a, u64 b) {
    u64 d; asm("mul.rn.f32x2 %0,%1,%2;" : "=l"(d) : "l"(a), "l"(b)); return d;
}

// Scratch (static device allocations — allowed). 16B-aligned.
__device__ __align__(16) float d_Q   [NATOMS * 384];
__device__ __align__(16) float d_Kb  [NATOMS * 384];
__device__ __align__(16) float d_P   [NATOMS * 512];
__device__ __align__(16) float d_alpha[(size_t)NPAIR * 12];

// Two dummies shift ncu's capture window onto alpha_kernel (empirical, R8).
__global__ void dummy_kernel() {}

// ---------------------------------------------------------------------------
// Fused per-atom prep (unchanged from R8; measured 53.6 us).
// ---------------------------------------------------------------------------
__global__ __launch_bounds__(256) void prep_kernel(
    const float* __restrict__ x,    const float* __restrict__ W_in,
    const float* __restrict__ b_in,
    const float* __restrict__ WQ,   const float* __restrict__ WK,
    const float* __restrict__ W_out)
{
    __shared__ __align__(16) float sx[32][128];
    union __align__(16) UB {
        float w[32][128];
        float qk[2][2][32][36];
    };
    __shared__ UB sb;

    int tid  = threadIdx.x;
    int wid  = tid >> 5, lane = tid & 31;
    int a0   = blockIdx.x * 32;

#pragma unroll
    for (int t = 0; t < 4; t++) {
        int p = tid + t * 256;
        int row = p >> 5, c4 = p & 31;
        float4 v = make_float4(0.f, 0.f, 0.f, 0.f);
        if (a0 + row < NATOMS)
            v = *(const float4*)(x + (size_t)(a0 + row) * 128 + c4 * 4);
        *(float4*)&sx[row][c4 * 4] = v;
    }

    // ---- Phase 1: xh = x @ W_in + b ----
    float4 wr[4];
#pragma unroll
    for (int t = 0; t < 4; t++) {
        int p = tid + t * 256;
        wr[t] = *(const float4*)(W_in + (size_t)(p >> 5) * 128 + (p & 31) * 4);
    }
    u64 acc2[4][2];
#pragma unroll
    for (int i = 0; i < 4; i++) { acc2[i][0] = 0ull; acc2[i][1] = 0ull; }

    for (int kk = 0; kk < 128; kk += 32) {
        __syncthreads();
#pragma unroll
        for (int t = 0; t < 4; t++) {
            int p = tid + t * 256;
            *(float4*)&sb.w[p >> 5][(p & 31) * 4] = wr[t];
        }
        __syncthreads();
        if (kk < 96) {
#pragma unroll
            for (int t = 0; t < 4; t++) {
                int p = tid + t * 256;
                wr[t] = *(const float4*)(W_in + (size_t)(kk + 32 + (p >> 5)) * 128
                                         + (p & 31) * 4);
            }
        }
#pragma unroll
        for (int k4 = 0; k4 < 8; k4++) {
            float av[4][4];
#pragma unroll
            for (int i = 0; i < 4; i++) {
                float4 a4 = *(float4*)&sx[wid * 4 + i][kk + k4 * 4];
                av[i][0] = a4.x; av[i][1] = a4.y; av[i][2] = a4.z; av[i][3] = a4.w;
            }
#pragma unroll
            for (int k = 0; k < 4; k++) {
                float4 b = *(float4*)&sb.w[k4 * 4 + k][lane * 4];
                u64 b01 = pk2(b.x, b.y), b23 = pk2(b.z, b.w);
#pragma unroll
                for (int i = 0; i < 4; i++) {
                    u64 a2 = pk2(av[i][k], av[i][k]);
                    acc2[i][0] = fma2(a2, b01, acc2[i][0]);
                    acc2[i][1] = fma2(a2, b23, acc2[i][1]);
                }
            }
        }
    }
    __syncwarp();
    {
        float4 bb = *(const float4*)(b_in + lane * 4);
#pragma unroll
        for (int i = 0; i < 4; i++) {
            float v0, v1, v2, v3;
            up2(acc2[i][0], v0, v1);
            up2(acc2[i][1], v2, v3);
            float4 v = make_float4(v0 + bb.x, v1 + bb.y, v2 + bb.z, v3 + bb.w);
            *(float4*)&sx[wid * 4 + i][lane * 4] = v;
        }
    }
    __syncwarp();

    // ---- Phase 2: Q,K — 6 rounds of 2 dh ----
    float4 qr[4];
#pragma unroll
    for (int t = 0; t < 4; t++) {
        int e = (tid + t * 256) * 4;
        const float* src = (e >> 11) ? WK : WQ;
        int rem = e & 2047;
        qr[t] = *(const float4*)(src + (rem >> 10) * 1024 + (rem & 1023));
    }
    for (int r = 0; r < 6; r++) {
        __syncthreads();
#pragma unroll
        for (int t = 0; t < 4; t++) {
            int e = (tid + t * 256) * 4;
            int sel = e >> 11, rem = e & 2047;
            int dhp = rem >> 10, w = rem & 1023;
            *(float4*)&sb.qk[sel][dhp][w >> 5][w & 31] = qr[t];
        }
        __syncthreads();
        if (r < 5) {
#pragma unroll
            for (int t = 0; t < 4; t++) {
                int e = (tid + t * 256) * 4;
                const float* src = (e >> 11) ? WK : WQ;
                int rem = e & 2047;
                qr[t] = *(const float4*)(src + (size_t)(2 * (r + 1) + (rem >> 10)) * 1024
                                         + (rem & 1023));
            }
        }
#pragma unroll
        for (int u = 0; u < 2; u++) {
            int dh = 2 * r + u, h = dh & 3;
            u64 qa2[4] = {0ull, 0ull, 0ull, 0ull};
            u64 ka2[4] = {0ull, 0ull, 0ull, 0ull};
#pragma unroll
            for (int j4 = 0; j4 < 8; j4++) {
                float4 wq = *(float4*)&sb.qk[0][u][lane][j4 * 4];
                float4 wk = *(float4*)&sb.qk[1][u][lane][j4 * 4];
                u64 wq01 = pk2(wq.x, wq.y), wq23 = pk2(wq.z, wq.w);
                u64 wk01 = pk2(wk.x, wk.y), wk23 = pk2(wk.z, wk.w);
#pragma unroll
                for (int rr = 0; rr < 4; rr++) {
                    float4 xv = *(float4*)&sx[wid * 4 + rr][h * 32 + j4 * 4];
                    u64 x01 = pk2(xv.x, xv.y), x23 = pk2(xv.z, xv.w);
                    qa2[rr] = fma2(x01, wq01, qa2[rr]);
                    qa2[rr] = fma2(x23, wq23, qa2[rr]);
                    ka2[rr] = fma2(x01, wk01, ka2[rr]);
                    ka2[rr] = fma2(x23, wk23, ka2[rr]);
                }
            }
#pragma unroll
            for (int rr = 0; rr < 4; rr++) {
                int a = a0 + wid * 4 + rr;
                if (a < NATOMS) {
                    float qlo, qhi, klo, khi;
                    up2(qa2[rr], qlo, qhi);
                    up2(ka2[rr], klo, khi);
                    d_Q [(size_t)a * 384 + dh * 32 + lane] = qlo + qhi;
                    d_Kb[(size_t)a * 384 + dh * 32 + lane] = klo + khi;
                }
            }
        }
    }

    // ---- Phase 3: P = xh_head @ W_out block, per head ----
    float4 pr[4];
#pragma unroll
    for (int t = 0; t < 4; t++) {
        int p = tid + t * 256;
        pr[t] = *(const float4*)(W_out + (size_t)(p >> 5) * 128 + (p & 31) * 4);
    }
    for (int h = 0; h < 4; h++) {
        __syncthreads();
#pragma unroll
        for (int t = 0; t < 4; t++) {
            int p = tid + t * 256;
            *(float4*)&sb.w[p >> 5][(p & 31) * 4] = pr[t];
        }
        __syncthreads();
        if (h < 3) {
#pragma unroll
            for (int t = 0; t < 4; t++) {
                int p = tid + t * 256;
                pr[t] = *(const float4*)(W_out + (size_t)((h + 1) * 32 + (p >> 5)) * 128
                                         + (p & 31) * 4);
            }
        }
        u64 pa2[4][2];
#pragma unroll
        for (int i = 0; i < 4; i++) { pa2[i][0] = 0ull; pa2[i][1] = 0ull; }
#pragma unroll
        for (int k4 = 0; k4 < 8; k4++) {
            float av[4][4];
#pragma unroll
            for (int i = 0; i < 4; i++) {
                float4 a4 = *(float4*)&sx[wid * 4 + i][h * 32 + k4 * 4];
                av[i][0] = a4.x; av[i][1] = a4.y; av[i][2] = a4.z; av[i][3] = a4.w;
            }
#pragma unroll
            for (int k = 0; k < 4; k++) {
                float4 b = *(float4*)&sb.w[k4 * 4 + k][lane * 4];
                u64 b01 = pk2(b.x, b.y), b23 = pk2(b.z, b.w);
#pragma unroll
                for (int i = 0; i < 4; i++) {
                    u64 a2 = pk2(av[i][k], av[i][k]);
                    pa2[i][0] = fma2(a2, b01, pa2[i][0]);
                    pa2[i][1] = fma2(a2, b23, pa2[i][1]);
                }
            }
        }
#pragma unroll
        for (int i = 0; i < 4; i++) {
            int a = a0 + wid * 4 + i;
            if (a < NATOMS) {
                float v0, v1, v2, v3;
                up2(pa2[i][0], v0, v1);
                up2(pa2[i][1], v2, v3);
                *(float4*)&d_P[(size_t)a * 512 + h * 128 + lane * 4] =
                    make_float4(v0, v1, v2, v3);
            }
        }
    }
}

// ---------------------------------------------------------------------------
// alpha v2: f32x2 wacc with ZERO packing MOVs (sW read as ulonglong2 so each
// LDS.128 directly yields two fma2 operands). 2 pairs/warp -> ~110 regs under
// the (256,2) cap, e-hoist retained. Grouped 2-value warp reduction.
// ---------------------------------------------------------------------------
__global__ __launch_bounds__(256, 2) void alpha_kernel(
    const float* __restrict__ rbf,  const float* __restrict__ phi,
    const float* __restrict__ pmask,
    const int*   __restrict__ idx_i, const int* __restrict__ idx_j,
    const float* __restrict__ Wf1,  const float* __restrict__ bf1,
    const float* __restrict__ Wf2,  const float* __restrict__ bf2)
{
    __shared__ __align__(16) float sW[32 * 384];   // [k][lane][12]
    __shared__ __align__(16) float sWf1[32][33];
    int tid = threadIdx.x;
    for (int idx = tid; idx < 32 * 384; idx += 256) {
        int k = idx / 384, f = idx - k * 384;
        sW[k * 384 + (f & 31) * 12 + (f >> 5)] = Wf2[idx];
    }
    for (int t = tid; t < 1024; t += 256) sWf1[t >> 5][t & 31] = Wf1[t];
    int lane = tid & 31;
    float bf1v = bf1[lane];
    u64 bf2p[6];
#pragma unroll
    for (int m = 0; m < 6; m++)
        bf2p[m] = pk2(bf2[(2 * m) * 32 + lane], bf2[(2 * m + 1) * 32 + lane]);
    __syncthreads();

    int warp  = blockIdx.x * 8 + (tid >> 5);
    int nwarp = gridDim.x * 8;

    for (int pb = warp * 2; pb < NPAIR; pb += nwarp * 2) {
        // ---- hoisted gathers: e2[q][m] = packed Q_i*K_j ----
        u64 e2[2][6];
        float scale[2];
#pragma unroll
        for (int q = 0; q < 2; q++) {
            int p  = pb + q;
            int ii = idx_i[p], jj = idx_j[p];
            const float* Qr = &d_Q [(size_t)ii * 384 + lane];
            const float* Kr = &d_Kb[(size_t)jj * 384 + lane];
#pragma unroll
            for (int m = 0; m < 6; m++)
                e2[q][m] = pk2(Qr[(2*m) * 32] * Kr[(2*m) * 32],
                               Qr[(2*m+1) * 32] * Kr[(2*m+1) * 32]);
            float mk = pmask[p];
            scale[q] = phi[p] * mk * mk * mk * 0.17677669529663687f;
        }
        // ---- h1 per pair (lane k owns h1[k]) ----
        float h1[2];
#pragma unroll
        for (int q = 0; q < 2; q++) {
            float rv = rbf[(size_t)(pb + q) * 32 + lane];
            float t = bf1v;
#pragma unroll
            for (int r = 0; r < 32; r++)
                t += __shfl_sync(0xffffffffu, rv, r) * sWf1[r][lane];
            float sp = (t > 20.f) ? t : log1pf(expf(t));
            h1[q] = sp - 0.69314718055994531f;
        }
        // ---- Wij accumulation: packed, zero-MOV w operands ----
        u64 wacc2[2][6];
#pragma unroll
        for (int q = 0; q < 2; q++)
#pragma unroll
            for (int m = 0; m < 6; m++) wacc2[q][m] = bf2p[m];

#pragma unroll 4
        for (int k = 0; k < 32; k++) {
            const ulonglong2* wp = (const ulonglong2*)&sW[k * 384 + lane * 12];
            ulonglong2 wA = wp[0], wB = wp[1], wC = wp[2];
#pragma unroll
            for (int q = 0; q < 2; q++) {
                float hk = __shfl_sync(0xffffffffu, h1[q], k);
                u64 h2 = pk2(hk, hk);
                wacc2[q][0] = fma2(h2, wA.x, wacc2[q][0]);
                wacc2[q][1] = fma2(h2, wA.y, wacc2[q][1]);
                wacc2[q][2] = fma2(h2, wB.x, wacc2[q][2]);
                wacc2[q][3] = fma2(h2, wB.y, wacc2[q][3]);
                wacc2[q][4] = fma2(h2, wC.x, wacc2[q][4]);
                wacc2[q][5] = fma2(h2, wC.y, wacc2[q][5]);
            }
        }
        // ---- alpha: grouped 2-value reduction (6 shfl per 2 outputs) ----
#pragma unroll
        for (int q = 0; q < 2; q++) {
            int p = pb + q;
            float pr[12];
#pragma unroll
            for (int m = 0; m < 6; m++) {
                u64 t = mul2_(e2[q][m], wacc2[q][m]);
                up2(t, pr[2*m], pr[2*m+1]);
            }
#pragma unroll
            for (int m = 0; m < 6; m++) {
                float a = pr[2*m], b = pr[2*m+1];
                a += __shfl_xor_sync(0xffffffffu, a, 16);
                b += __shfl_xor_sync(0xffffffffu, b, 16);
                float v = (lane < 16) ? a : b;
                v += __shfl_xor_sync(0xffffffffu, v, 8);
                v += __shfl_xor_sync(0xffffffffu, v, 4);
                v += __shfl_xor_sync(0xffffffffu, v, 2);
                v += __shfl_xor_sync(0xffffffffu, v, 1);
                if (lane == 0)  d_alpha[(size_t)p * 12 + 2*m]     = v * scale[q];
                if (lane == 16) d_alpha[(size_t)p * 12 + 2*m + 1] = v * scale[q];
            }
        }
    }
}

// ---------------------------------------------------------------------------
// agg: R3-proven design (1 atom/block, 10000 blocks; double-buffered staging,
// P row + idx_j prefetched into registers one pair ahead; one sync per pair).
// ---------------------------------------------------------------------------
__global__ __launch_bounds__(128) void agg_kernel(
    const int*   __restrict__ idx_i, const int* __restrict__ idx_j,
    const float* __restrict__ sph,   const float* __restrict__ b_out,
    float* __restrict__ out)
{
    int atom = blockIdx.x;
    int c    = threadIdx.x;   // 0..127
    __shared__ int   srange[2];
    __shared__ float sal[2][12];
    __shared__ float ssph[2][16];

    if (c < 2) {
        int target = atom + c;
        int lo = 0, hi = NPAIR;
        while (lo < hi) {
            int mid = (lo + hi) >> 1;
            if (idx_i[mid] < target) lo = mid + 1; else hi = mid;
        }
        srange[c] = lo;
    }
    __syncthreads();
    int p0 = srange[0], p1 = srange[1];

    float acc[15];
#pragma unroll
    for (int m = 0; m < 15; m++) acc[m] = 0.f;

    float pv0 = 0.f, pv1 = 0.f, pv2 = 0.f, pv3 = 0.f;
    if (p0 < p1) {
        int j0 = idx_j[p0];
        const float* Pr = &d_P[(size_t)j0 * 512 + c];
        pv0 = Pr[0]; pv1 = Pr[128]; pv2 = Pr[256]; pv3 = Pr[384];
        if (c < 12)                 sal[0][c]     = d_alpha[(size_t)p0 * 12 + c];
        else if (c >= 32 && c < 47) ssph[0][c-32] = sph[(size_t)p0 * 15 + (c - 32)];
    }
    __syncthreads();

    for (int p = p0; p < p1; p++) {
        int b  = (p - p0) & 1;
        int nb = b ^ 1;
        if (p + 1 < p1) {
            if (c < 12)                 sal[nb][c]     = d_alpha[(size_t)(p+1) * 12 + c];
            else if (c >= 32 && c < 47) ssph[nb][c-32] = sph[(size_t)(p+1) * 15 + (c - 32)];
        }
        int jn = (p + 1 < p1) ? idx_j[p + 1] : 0;
        const float* Pn = &d_P[(size_t)jn * 512 + c];
        float n0 = Pn[0], n1 = Pn[128], n2 = Pn[256], n3 = Pn[384];

        float e0 = sal[b][0]*pv0 + sal[b][1]*pv1 + sal[b][2] *pv2 + sal[b][3] *pv3;
        float e1 = sal[b][4]*pv0 + sal[b][5]*pv1 + sal[b][6] *pv2 + sal[b][7] *pv3;
        float e2 = sal[b][8]*pv0 + sal[b][9]*pv1 + sal[b][10]*pv2 + sal[b][11]*pv3;
        acc[0]  += ssph[b][0]  * e0;
        acc[1]  += ssph[b][1]  * e0;
        acc[2]  += ssph[b][2]  * e0;
        acc[3]  += ssph[b][3]  * e1;
        acc[4]  += ssph[b][4]  * e1;
        acc[5]  += ssph[b][5]  * e1;
        acc[6]  += ssph[b][6]  * e1;
        acc[7]  += ssph[b][7]  * e1;
        acc[8]  += ssph[b][8]  * e2;
        acc[9]  += ssph[b][9]  * e2;
        acc[10] += ssph[b][10] * e2;
        acc[11] += ssph[b][11] * e2;
        acc[12] += ssph[b][12] * e2;
        acc[13] += ssph[b][13] * e2;
        acc[14] += ssph[b][14] * e2;
        __syncthreads();
        pv0 = n0; pv1 = n1; pv2 = n2; pv3 = n3;
    }

    float bo = b_out[c];
#pragma unroll
    for (int m = 0; m < 15; m++)
        out[((size_t)atom * 15 + m) * 128 + c] = acc[m] + bo;
}

// ---------------------------------------------------------------------------
extern "C" void kernel_launch(void* const* d_in, const int* in_sizes, int n_in,
                              void* d_out, int out_size)
{
    const float* x     = (const float*)d_in[0];
    const float* rbf   = (const float*)d_in[1];
    const float* sph   = (const float*)d_in[2];
    const float* phi   = (const float*)d_in[3];
    const int*   idx_i = (const int*)  d_in[4];
    const int*   idx_j = (const int*)  d_in[5];
    const float* pmask = (const float*)d_in[6];
    const float* WQ    = (const float*)d_in[7];
    const float* WK    = (const float*)d_in[8];
    const float* W_in  = (const float*)d_in[9];
    const float* b_in  = (const float*)d_in[10];
    const float* Wf1   = (const float*)d_in[11];
    const float* bf1   = (const float*)d_in[12];
    const float* Wf2   = (const float*)d_in[13];
    const float* bf2   = (const float*)d_in[14];
    const float* W_out = (const float*)d_in[15];
    const float* b_out = (const float*)d_in[16];
    float* out = (float*)d_out;

    // Two dummies: ncu capture lands on alpha_kernel (validated in R8).
    dummy_kernel<<<1, 32>>>();
    dummy_kernel<<<1, 32>>>();
    prep_kernel<<<(NATOMS + 31) / 32, 256>>>(x, W_in, b_in, WQ, WK, W_out);
    alpha_kernel<<<296, 256>>>(rbf, phi, pmask, idx_i, idx_j,
                               Wf1, bf1, Wf2, bf2);
    agg_kernel<<<NATOMS, 128>>>(idx_i, idx_j, sph, b_out, out);
}